// round 15
// baseline (speedup 1.0000x reference)
#include <cuda_runtime.h>
#include <math.h>

#define THREADS 256
#define RPT 2                      // rows per thread per stage
#define TILE (THREADS * RPT)       // 512 rows per tile
#define NSTAGE 4
#define KC 32
#define DD 8
#define STAGE_FLOATS (TILE * DD)   // 4096 floats = 16KB
#define STAGE_BYTES (STAGE_FLOATS * 4)

__device__ double g_sum;                 // zero-init at load; reset by last block each run
__device__ unsigned int g_counts[KC];
__device__ unsigned int g_done;

static __device__ __forceinline__ unsigned long long pk2(float lo, float hi) {
    unsigned long long r;
    asm("mov.b64 %0, {%1,%2};" : "=l"(r) : "f"(lo), "f"(hi));
    return r;
}
static __device__ __forceinline__ void upk2(unsigned long long v, float& lo, float& hi) {
    asm("mov.b64 {%0,%1}, %2;" : "=f"(lo), "=f"(hi) : "l"(v));
}
static __device__ __forceinline__ unsigned long long ffma2(unsigned long long a,
                                                           unsigned long long b,
                                                           unsigned long long c) {
    unsigned long long r;
    asm("fma.rn.f32x2 %0, %1, %2, %3;" : "=l"(r) : "l"(a), "l"(b), "l"(c));
    return r;
}
static __device__ __forceinline__ unsigned int smem_u32(const void* p) {
    unsigned int a;
    asm("{ .reg .u64 t; cvta.to.shared.u64 t, %1; cvt.u32.u64 %0, t; }" : "=r"(a) : "l"(p));
    return a;
}
static __device__ __forceinline__ void mbar_init(unsigned int mb, unsigned int cnt) {
    asm volatile("mbarrier.init.shared.b64 [%0], %1;" :: "r"(mb), "r"(cnt) : "memory");
}
static __device__ __forceinline__ void mbar_wait(unsigned int mb, unsigned int phase) {
    asm volatile(
        "{\n\t"
        ".reg .pred P1;\n\t"
        "WAIT_LOOP_%=:\n\t"
        "mbarrier.try_wait.parity.acquire.cta.shared::cta.b64 P1, [%0], %1, 0x989680;\n\t"
        "@P1 bra.uni WAIT_DONE_%=;\n\t"
        "bra.uni WAIT_LOOP_%=;\n\t"
        "WAIT_DONE_%=:\n\t"
        "}"
        :: "r"(mb), "r"(phase) : "memory");
}
// one thread: post expect_tx and launch the bulk async copy for tile t into stage s
static __device__ __forceinline__ void issue_tile(
    const float* __restrict__ z, int nrows, unsigned int zbase, unsigned int mbase,
    long long t, int s)
{
    long long r0 = t * TILE;
    long long rem = (long long)nrows - r0;
    int rows = rem < TILE ? (int)rem : TILE;
    unsigned int bytes = (unsigned int)rows * (DD * 4);
    unsigned int mb = mbase + s * 8;
    unsigned int dst = zbase + s * STAGE_BYTES;
    const float* src = z + r0 * DD;
    asm volatile("mbarrier.arrive.expect_tx.shared.b64 _, [%0], %1;"
                 :: "r"(mb), "r"(bytes) : "memory");
    asm volatile("cp.async.bulk.shared::cluster.global.mbarrier::complete_tx::bytes "
                 "[%0], [%1], %2, [%3];"
                 :: "r"(dst), "l"(src), "r"(bytes), "r"(mb) : "memory");
}

__global__ __launch_bounds__(THREADS) void vq_fused(
    const float* __restrict__ z, const float* __restrict__ cb,
    float* __restrict__ out, int nrows, long long ndelem, int write_scalars)
{
    extern __shared__ float s_z[];                  // NSTAGE x STAGE_FLOATS
    __shared__ unsigned long long s_mbar[NSTAGE];
    __shared__ float s_mk[KC][12];                  // [0..7]=-2c_d, [8]=||c||^2
    __shared__ float2 s_cpair[KC][5];               // raw code row, stride 5
    __shared__ unsigned int s_cnt[KC];
    __shared__ double s_red[THREADS / 32];
    __shared__ int s_islast;

    const int tid = threadIdx.x;
    const int lane = tid & 31;

    if (tid < KC) {
        float cn = 0.f;
#pragma unroll
        for (int d = 0; d < DD; d++) {
            float v = cb[tid * DD + d];
            s_mk[tid][d] = -2.f * v;
            cn = fmaf(v, v, cn);
            if ((d & 1) == 0) s_cpair[tid][d >> 1].x = v;
            else              s_cpair[tid][d >> 1].y = v;
        }
        s_mk[tid][8] = cn;
        s_cnt[tid] = 0u;
    }

    const unsigned int zbase = smem_u32(s_z);
    const unsigned int mbase = smem_u32(s_mbar);
    if (tid == 0) {
#pragma unroll
        for (int s = 0; s < NSTAGE; ++s) mbar_init(mbase + s * 8, 1u);
        asm volatile("fence.proxy.async.shared::cta;" ::: "memory");
    }
    __syncthreads();   // codebook + mbarrier init visible

    const long long ntiles = ((long long)nrows + TILE - 1) / TILE;
    const long long stride = gridDim.x;

    // prefill pipeline
    if (tid == 0) {
#pragma unroll
        for (int s = 0; s < NSTAGE; ++s) {
            long long t = blockIdx.x + (long long)s * stride;
            if (t < ntiles) issue_tile(z, nrows, zbase, mbase, t, s);
        }
    }

    float lsum = 0.f;
    int it = 0;
    for (long long t = blockIdx.x; t < ntiles; t += stride, ++it) {
        const int s = it & (NSTAGE - 1);
        const unsigned int phase = (unsigned int)((it >> 2) & 1);
        mbar_wait(mbase + s * 8, phase);

        const float* zs = s_z + s * STAGE_FLOATS;
        const long long tbase = t * TILE + tid;

        // ---- read rows from smem stage; float4 pairs ARE dim-packed f32x2 regs ----
        unsigned long long zr[RPT][4];
        bool valid[RPT];
#pragma unroll
        for (int r = 0; r < RPT; ++r) {
            int local = tid + r * THREADS;
            valid[r] = (tbase + (long long)r * THREADS) < (long long)nrows;
            float4 a0 = *(const float4*)(zs + local * DD);
            float4 a1 = *(const float4*)(zs + local * DD + 4);
            ulonglong2 u0 = *(ulonglong2*)&a0;   // (z0,z1),(z2,z3)
            ulonglong2 u1 = *(ulonglong2*)&a1;   // (z4,z5),(z6,z7)
            zr[r][0] = u0.x; zr[r][1] = u0.y;
            zr[r][2] = u1.x; zr[r][3] = u1.y;
        }

        float best[RPT];
        int   bi[RPT];
#pragma unroll
        for (int i = 0; i < RPT; i++) { best[i] = 3.4e38f; bi[i] = 0; }

        // ---- argmin over 32 codes: dist-z2 = ||c||^2 + sum((-2c_d) z_d) ----
#pragma unroll 4
        for (int k = 0; k < KC; k++) {
            ulonglong2 A = *(const ulonglong2*)&s_mk[k][0];
            ulonglong2 B = *(const ulonglong2*)&s_mk[k][4];
            float cn = s_mk[k][8];
            unsigned long long init = pk2(cn, 0.f);
#pragma unroll
            for (int r = 0; r < RPT; r++) {
                unsigned long long acc = ffma2(zr[r][0], A.x, init);
                acc = ffma2(zr[r][1], A.y, acc);
                acc = ffma2(zr[r][2], B.x, acc);
                acc = ffma2(zr[r][3], B.y, acc);
                float lo, hi;
                upk2(acc, lo, hi);
                float d = lo + hi;
                if (d < best[r]) { best[r] = d; bi[r] = k; }
            }
        }

        // ---- epilogue: loss = sum((c-z)^2) exact, out = z + (c - z) ----
#pragma unroll
        for (int r = 0; r < RPT; r++) {
            if (!valid[r]) continue;
            const int bk = bi[r];
            float2 c0 = s_cpair[bk][0], c1 = s_cpair[bk][1],
                   c2 = s_cpair[bk][2], c3 = s_cpair[bk][3];
            float zv[DD];
            upk2(zr[r][0], zv[0], zv[1]);
            upk2(zr[r][1], zv[2], zv[3]);
            upk2(zr[r][2], zv[4], zv[5]);
            upk2(zr[r][3], zv[6], zv[7]);
            float cv[DD] = {c0.x, c0.y, c1.x, c1.y, c2.x, c2.y, c3.x, c3.y};
            float ov[DD];
            float sacc = 0.f;
#pragma unroll
            for (int d = 0; d < DD; d++) {
                float df = cv[d] - zv[d];
                ov[d] = zv[d] + df;    // z + (z_q - z), matches reference FP order
                sacc = fmaf(df, df, sacc);
            }
            lsum += sacc;
            long long row = tbase + (long long)r * THREADS;
            *(float4*)(out + row * DD)     = make_float4(ov[0], ov[1], ov[2], ov[3]);
            *(float4*)(out + row * DD + 4) = make_float4(ov[4], ov[5], ov[6], ov[7]);
        }

        // warp-aggregated histogram (integer-exact)
#pragma unroll
        for (int r = 0; r < RPT; r++) {
            unsigned int key = valid[r] ? (unsigned int)bi[r] : 0xFFFFFFFFu;
            unsigned int grp = __match_any_sync(0xffffffffu, key);
            bool leader = ((grp & ((1u << lane) - 1u)) == 0u);
            if (valid[r] && leader) atomicAdd(&s_cnt[bi[r]], (unsigned int)__popc(grp));
        }

        // stage fully consumed by all threads -> refill with tile t + NSTAGE*stride
        __syncthreads();
        if (tid == 0) {
            long long tn = t + (long long)NSTAGE * stride;
            if (tn < ntiles) issue_tile(z, nrows, zbase, mbase, tn, s);
        }
    }

    // ---- once per block: reductions -> global accumulators ----
#pragma unroll
    for (int off = 16; off; off >>= 1)
        lsum += __shfl_down_sync(0xffffffffu, lsum, off);
    if ((tid & 31) == 0) s_red[tid >> 5] = (double)lsum;
    __syncthreads();
    if (tid == 0) {
        double tsum = 0.0;
#pragma unroll
        for (int w = 0; w < THREADS / 32; w++) tsum += s_red[w];
        atomicAdd(&g_sum, tsum);
    }
    if (tid < KC) {
        unsigned int c = s_cnt[tid];
        if (c) atomicAdd(&g_counts[tid], c);
    }

    // ---- last-block finalize (threadfence + ticket pattern) ----
    __syncthreads();
    if (tid == 0) {
        __threadfence();
        unsigned int ticket = atomicAdd(&g_done, 1u);
        s_islast = (ticket == gridDim.x - 1) ? 1 : 0;
    }
    __syncthreads();

    if (s_islast && tid < 32) {
        unsigned int cnt = g_counts[tid];
        double p = (double)cnt / (double)nrows;
        double term = p * log(p + 1e-10);
#pragma unroll
        for (int off = 16; off; off >>= 1)
            term += __shfl_down_sync(0xffffffffu, term, off);
        if (tid == 0) {
            double ssum = atomicAdd(&g_sum, 0.0);   // atomic read
            if (write_scalars) {
                out[ndelem]     = (float)((ssum * 1.25) / (double)ndelem);
                out[ndelem + 1] = (float)exp(-term);
            }
            g_sum = 0.0;                             // reset for next graph replay
        }
        g_counts[tid] = 0u;
        __threadfence();
        if (tid == 0) g_done = 0u;
    }
}

extern "C" void kernel_launch(void* const* d_in, const int* in_sizes, int n_in,
                              void* d_out, int out_size) {
    const float* z  = (const float*)d_in[0];
    const float* cb = (const float*)d_in[1];
    float* out = (float*)d_out;

    int nrows = in_sizes[0] / DD;
    long long ndelem = (long long)nrows * DD;
    long long ntiles = ((long long)nrows + TILE - 1) / TILE;
    int write_scalars = ((long long)out_size >= ndelem + 2) ? 1 : 0;

    const int dyn_smem = NSTAGE * STAGE_BYTES;      // 64KB
    cudaFuncSetAttribute(vq_fused, cudaFuncAttributeMaxDynamicSharedMemorySize, dyn_smem);

    int cta_per_sm = 0, nsm = 0;
    cudaOccupancyMaxActiveBlocksPerMultiprocessor(&cta_per_sm, vq_fused, THREADS, dyn_smem);
    cudaDeviceGetAttribute(&nsm, cudaDevAttrMultiProcessorCount, 0);
    if (cta_per_sm <= 0) cta_per_sm = 3;
    if (nsm <= 0) nsm = 148;
    long long blocks = (long long)cta_per_sm * nsm;
    if (blocks > ntiles) blocks = ntiles;

    vq_fused<<<(int)blocks, THREADS, dyn_smem>>>(z, cb, out, nrows, ndelem, write_scalars);
}

// round 16
// speedup vs baseline: 1.1609x; 1.1609x over previous
#include <cuda_runtime.h>
#include <math.h>

#define THREADS 256
#define RPT 2            // rows per thread
#define TILE (THREADS * RPT)
#define KC 32            // codebook size
#define DD 8             // codebook dim

__device__ double g_sum;                 // zero-init at load; reset by last block each run
__device__ unsigned int g_counts[KC];
__device__ unsigned int g_done;

static __device__ __forceinline__ unsigned long long pk2(float lo, float hi) {
    unsigned long long r;
    asm("mov.b64 %0, {%1,%2};" : "=l"(r) : "f"(lo), "f"(hi));
    return r;
}
static __device__ __forceinline__ void upk2(unsigned long long v, float& lo, float& hi) {
    asm("mov.b64 {%0,%1}, %2;" : "=f"(lo), "=f"(hi) : "l"(v));
}
// packed f32x2 fma: d.lo = a.lo*b.lo + c.lo ; d.hi = a.hi*b.hi + c.hi
static __device__ __forceinline__ unsigned long long ffma2(unsigned long long a,
                                                           unsigned long long b,
                                                           unsigned long long c) {
    unsigned long long r;
    asm("fma.rn.f32x2 %0, %1, %2, %3;" : "=l"(r) : "l"(a), "l"(b), "l"(c));
    return r;
}

__global__ __launch_bounds__(THREADS, 5) void vq_fused(
    const float* __restrict__ z, const float* __restrict__ cb,
    float* __restrict__ out, int nrows, long long ndelem, int write_scalars)
{
    // Dim-packed codebook: s_mk[k][0..7] = -2*c_d (natural order -> 2x LDS.128),
    // s_mk[k][8] = ||c||^2. Stride 12 floats keeps rows 16B-aligned.
    __shared__ float s_mk[KC][12];
    __shared__ float2 s_cpair[KC][5];    // raw code row, stride 5 -> bank-safe gather
    __shared__ unsigned int s_cnt[KC];
    __shared__ double s_red[THREADS / 32];
    __shared__ int s_islast;

    const int tid = threadIdx.x;
    const int lane = tid & 31;

    if (tid < KC) {
        float cn = 0.f;
#pragma unroll
        for (int d = 0; d < DD; d++) {
            float v = cb[tid * DD + d];
            s_mk[tid][d] = -2.f * v;
            cn = fmaf(v, v, cn);
            if ((d & 1) == 0) s_cpair[tid][d >> 1].x = v;
            else              s_cpair[tid][d >> 1].y = v;
        }
        s_mk[tid][8] = cn;
        s_cnt[tid] = 0u;
    }
    __syncthreads();

    const long long base = (long long)blockIdx.x * TILE + tid;

    // ---- load RPT rows; float4 pairs ARE dim-packed f32x2 registers ----
    unsigned long long zr[RPT][4];
    bool valid[RPT];
#pragma unroll
    for (int r = 0; r < RPT; ++r) {
        long long row = base + (long long)r * THREADS;
        valid[r] = (row < nrows);
        long long lr = valid[r] ? row : 0;
        float4 a0 = *(const float4*)(z + lr * DD);
        float4 a1 = *(const float4*)(z + lr * DD + 4);
        ulonglong2 u0 = *(ulonglong2*)&a0;   // (z0,z1),(z2,z3)
        ulonglong2 u1 = *(ulonglong2*)&a1;   // (z4,z5),(z6,z7)
        zr[r][0] = u0.x; zr[r][1] = u0.y;
        zr[r][2] = u1.x; zr[r][3] = u1.y;
    }

    float best[RPT];
    int   bi[RPT];
#pragma unroll
    for (int i = 0; i < RPT; i++) { best[i] = 3.4e38f; bi[i] = 0; }

    // ---- argmin over 32 codes: dist-z2 = ||c||^2 + sum((-2c_d) z_d) ----
#pragma unroll 4
    for (int k = 0; k < KC; k++) {
        ulonglong2 A = *(const ulonglong2*)&s_mk[k][0];
        ulonglong2 B = *(const ulonglong2*)&s_mk[k][4];
        float cn = s_mk[k][8];
        unsigned long long init = pk2(cn, 0.f);
#pragma unroll
        for (int r = 0; r < RPT; r++) {
            unsigned long long acc = ffma2(zr[r][0], A.x, init);
            acc = ffma2(zr[r][1], A.y, acc);
            acc = ffma2(zr[r][2], B.x, acc);
            acc = ffma2(zr[r][3], B.y, acc);
            float lo, hi;
            upk2(acc, lo, hi);
            float d = lo + hi;
            if (d < best[r]) { best[r] = d; bi[r] = k; }
        }
    }

    // ---- epilogue: loss = Σ(c−z)^2 (exact), out = z + (c − z) ----
    float lsum = 0.f;
#pragma unroll
    for (int r = 0; r < RPT; r++) {
        if (!valid[r]) continue;
        const int b = bi[r];
        float2 c0 = s_cpair[b][0], c1 = s_cpair[b][1],
               c2 = s_cpair[b][2], c3 = s_cpair[b][3];
        float zv[DD];
        upk2(zr[r][0], zv[0], zv[1]);
        upk2(zr[r][1], zv[2], zv[3]);
        upk2(zr[r][2], zv[4], zv[5]);
        upk2(zr[r][3], zv[6], zv[7]);
        float cv[DD] = {c0.x, c0.y, c1.x, c1.y, c2.x, c2.y, c3.x, c3.y};
        float ov[DD];
        float s = 0.f;
#pragma unroll
        for (int d = 0; d < DD; d++) {
            float df = cv[d] - zv[d];
            ov[d] = zv[d] + df;    // z + (z_q - z), matches reference FP order
            s = fmaf(df, df, s);
        }
        lsum += s;
        long long row = base + (long long)r * THREADS;
        *(float4*)(out + row * DD)     = make_float4(ov[0], ov[1], ov[2], ov[3]);
        *(float4*)(out + row * DD + 4) = make_float4(ov[4], ov[5], ov[6], ov[7]);
    }

    // warp-aggregated histogram (integer-exact)
#pragma unroll
    for (int r = 0; r < RPT; r++) {
        unsigned int key = valid[r] ? (unsigned int)bi[r] : 0xFFFFFFFFu;
        unsigned int grp = __match_any_sync(0xffffffffu, key);
        bool leader = ((grp & ((1u << lane) - 1u)) == 0u);
        if (valid[r] && leader) atomicAdd(&s_cnt[bi[r]], (unsigned int)__popc(grp));
    }

    // ---- block reductions -> global accumulators ----
#pragma unroll
    for (int off = 16; off; off >>= 1)
        lsum += __shfl_down_sync(0xffffffffu, lsum, off);
    if ((tid & 31) == 0) s_red[tid >> 5] = (double)lsum;
    __syncthreads();
    if (tid == 0) {
        double t = 0.0;
#pragma unroll
        for (int w = 0; w < THREADS / 32; w++) t += s_red[w];
        atomicAdd(&g_sum, t);
    }
    if (tid < KC) {
        unsigned int c = s_cnt[tid];
        if (c) atomicAdd(&g_counts[tid], c);
    }

    // ---- last-block finalize (threadfence + ticket pattern) ----
    __syncthreads();                 // all atomics above issued
    if (tid == 0) {
        __threadfence();             // make this block's contributions device-visible
        unsigned int ticket = atomicAdd(&g_done, 1u);
        s_islast = (ticket == gridDim.x - 1) ? 1 : 0;
    }
    __syncthreads();

    if (s_islast && tid < 32) {
        unsigned int cnt = g_counts[tid];
        double p = (double)cnt / (double)nrows;
        double term = p * log(p + 1e-10);
#pragma unroll
        for (int off = 16; off; off >>= 1)
            term += __shfl_down_sync(0xffffffffu, term, off);
        if (tid == 0) {
            double s = atomicAdd(&g_sum, 0.0);   // atomic read
            if (write_scalars) {
                out[ndelem]     = (float)((s * 1.25) / (double)ndelem);
                out[ndelem + 1] = (float)exp(-term);
            }
            g_sum = 0.0;                          // reset for next graph replay
        }
        g_counts[tid] = 0u;
        __threadfence();
        if (tid == 0) g_done = 0u;
    }
}

extern "C" void kernel_launch(void* const* d_in, const int* in_sizes, int n_in,
                              void* d_out, int out_size) {
    const float* z  = (const float*)d_in[0];
    const float* cb = (const float*)d_in[1];
    float* out = (float*)d_out;

    int nrows = in_sizes[0] / DD;
    long long ndelem = (long long)nrows * DD;
    int blocks = (nrows + TILE - 1) / TILE;
    int write_scalars = ((long long)out_size >= ndelem + 2) ? 1 : 0;

    vq_fused<<<blocks, THREADS>>>(z, cb, out, nrows, ndelem, write_scalars);
}